// round 7
// baseline (speedup 1.0000x reference)
#include <cuda_runtime.h>
#include <cstdint>

// Problem constants
#define BB   8
#define CCH  64
#define HW   96
#define NL   2209      // 47*47 query/key patches
#define LPAD 2304      // padded to 18*128
#define DIM  1600      // 64*5*5 descriptor
#define NE   576       // 64*3*3 value patch dim
#define MAXFLAG 4096
#define MARGIN_TH 3e-4f
#define TIE_ZONE 8e-8  // fp64 gap below which we defer to first-occurrence rule

#define QTILE 128
#define LTILE 128
#define NLT   18
#define KC    32              // floats per K-chunk
#define NCHUNK (DIM/KC)       // 50
#define KSTR  36              // smem row stride in floats (bank-conflict-free)
#define ARRF  (128*KSTR)      // floats per matrix panel (4608)
#define ARRB  (ARRF*4)        // bytes (18432)
#define BUFB  (4*ARRB)        // 4 panels per buffer (73728)
#define SMEM_DYN (2*BUFB)     // double buffered (147456)

// Scratch (zero-initialized .bss; rows [NL, LPAD) stay zero)
__device__ float g_Qn [(size_t)BB * LPAD * DIM];   // exact normalized (refine)
__device__ float g_Kn [(size_t)BB * LPAD * DIM];
__device__ float g_Khi[(size_t)BB * LPAD * DIM];
__device__ float g_Klo[(size_t)BB * LPAD * DIM];
__device__ float g_Qhi[(size_t)BB * LPAD * DIM];
__device__ float g_Qlo[(size_t)BB * LPAD * DIM];
__device__ int   g_arg[BB * NL];
__device__ int   g_nflag;
__device__ int4  g_flag[MAXFLAG];   // {b, q, best_idx, second_idx}

// ---------------------------------------------------------------------------
__device__ __forceinline__ uint32_t smem_u32(const void* p) {
    uint32_t a;
    asm("{ .reg .u64 t; cvta.to.shared.u64 t, %1; cvt.u32.u64 %0, t; }" : "=r"(a) : "l"(p));
    return a;
}

#define CP_ASYNC16(saddr, gptr) \
    asm volatile("cp.async.cg.shared.global [%0], [%1], 16;" :: "r"(saddr), "l"(gptr) : "memory")
#define CP_COMMIT() asm volatile("cp.async.commit_group;" ::: "memory")
#define CP_WAIT0()  asm volatile("cp.async.wait_group 0;" ::: "memory")

#define MMA_TF32(c, a, b) \
    asm volatile( \
        "mma.sync.aligned.m16n8k8.row.col.f32.tf32.tf32.f32 " \
        "{%0,%1,%2,%3}, {%4,%5,%6,%7}, {%8,%9}, {%0,%1,%2,%3};" \
        : "+f"((c)[0]), "+f"((c)[1]), "+f"((c)[2]), "+f"((c)[3]) \
        : "r"((a)[0]), "r"((a)[1]), "r"((a)[2]), "r"((a)[3]), \
          "r"((b)[0]), "r"((b)[1]))

__device__ __forceinline__ void top2_merge(float& bv, int& bi, float& sv, int& si,
                                           float v, int iv, float v2, int i2) {
    if (v > bv || (v == bv && iv < bi)) {
        float ob = bv; int oi = bi;
        bv = v; bi = iv;
        if (ob > v2 || (ob == v2 && oi < i2)) { sv = ob; si = oi; }
        else { sv = v2; si = i2; }
    } else {
        if (v > sv || (v == sv && iv < si)) { sv = v; si = iv; }
    }
}

// ---------------------------------------------------------------------------
// Prep: unfold(5,1,2) + L2 normalize (fp64 norm); write exact + tf32 hi/lo.
// ---------------------------------------------------------------------------
__global__ __launch_bounds__(256) void prep_kernel(const float* __restrict__ queue,
                                                   const float* __restrict__ key) {
    int l = blockIdx.x;
    int b = blockIdx.y;
    bool isK = (blockIdx.z != 0);
    int t = threadIdx.x;
    if (blockIdx.x == 0 && blockIdx.y == 0 && blockIdx.z == 0 && t == 0) g_nflag = 0;

    const float* src = (isK ? key : queue) + (size_t)b * CCH * HW * HW;
    size_t ro = ((size_t)b * LPAD + l) * DIM;
    float* dx = (isK ? g_Kn : g_Qn) + ro;
    float* dh = (isK ? g_Khi : g_Qhi) + ro;
    float* dl = (isK ? g_Klo : g_Qlo) + ro;

    int pi = l / 47, pj = l % 47;
    int r0 = pi * 2 - 1, c0 = pj * 2 - 1;

    float vals[7];
    double ss = 0.0;
#pragma unroll
    for (int it = 0; it < 7; it++) {
        int e = t + it * 256;
        float v = 0.f;
        if (e < DIM) {
            int c = e / 25, kk = e % 25;
            int r = r0 + kk / 5, cc = c0 + kk % 5;
            if ((unsigned)r < HW && (unsigned)cc < HW)
                v = src[((size_t)c * HW + r) * HW + cc];
        }
        vals[it] = v;
        ss += (double)v * (double)v;
    }

    __shared__ double red[256];
    red[t] = ss;
    __syncthreads();
    for (int s = 128; s >= 1; s >>= 1) {
        if (t < s) red[t] += red[t + s];
        __syncthreads();
    }
    float n = (float)sqrt(red[0]);
    if (n < 1e-12f) n = 1e-12f;

#pragma unroll
    for (int it = 0; it < 7; it++) {
        int e = t + it * 256;
        if (e < DIM) {
            float x = vals[it] / n;
            uint32_t hb; asm("cvt.rna.tf32.f32 %0, %1;" : "=r"(hb) : "f"(x));
            float h = __uint_as_float(hb);
            float lo = x - h;
            uint32_t lb; asm("cvt.rna.tf32.f32 %0, %1;" : "=r"(lb) : "f"(lo));
            dx[e] = x;
            dh[e] = h;
            dl[e] = __uint_as_float(lb);
        }
    }
}

// ---------------------------------------------------------------------------
// Fused correlation GEMM (3xTF32 mma.sync) + column top-2 max/argmax.
// 256 threads (8 warps). Block tile 128L x 128Q; warp tile 64x32.
// K streamed in 32-float chunks via cp.async double buffering.
// ---------------------------------------------------------------------------
__global__ __launch_bounds__(256, 1) void corr_kernel(float* __restrict__ S) {
    int b  = blockIdx.y;
    int q0 = blockIdx.x * QTILE;
    const float* KH = g_Khi + (size_t)b * LPAD * DIM;
    const float* KL = g_Klo + (size_t)b * LPAD * DIM;
    const float* QH = g_Qhi + (size_t)b * LPAD * DIM;
    const float* QL = g_Qlo + (size_t)b * LPAD * DIM;

    extern __shared__ float smf[];           // 2 buffers x 4 panels x 128 x 36
    __shared__ float s2v[2][128], s2v2[2][128];
    __shared__ int   s2i[2][128], s2i2[2][128];
    __shared__ float s_runv[128], s_runv2[128];
    __shared__ int   s_runi[128], s_runi2[128];

    uint32_t sbase = smem_u32(smf);

    int tid = threadIdx.x;
    int wid = tid >> 5, lane = tid & 31;
    int g = lane >> 2, tig = lane & 3;
    int warp_m = wid >> 2;                   // 0..1 -> L halves
    int warp_n = wid & 3;                    // 0..3 -> Q quarters
    int lrow = tid & 127, half = tid >> 7;   // loader mapping

    if (tid < 128) {
        s_runv[tid] = -3.0e38f; s_runv2[tid] = -3.0e38f;
        s_runi[tid] = 0; s_runi2[tid] = 0;
    }
    __syncthreads();

    for (int lt = 0; lt < NLT; lt++) {
        int l0 = lt * LTILE;

        // ---- prologue: chunk 0 -> buffer 0
        {
            size_t ko = (size_t)half * 16;
            const float* pk0 = KH + (size_t)(l0 + lrow) * DIM + ko;
            const float* pk1 = KL + (size_t)(l0 + lrow) * DIM + ko;
            const float* pq0 = QH + (size_t)(q0 + lrow) * DIM + ko;
            const float* pq1 = QL + (size_t)(q0 + lrow) * DIM + ko;
            uint32_t so = sbase + lrow * (KSTR * 4) + half * 64;
#pragma unroll
            for (int j = 0; j < 4; j++) {
                CP_ASYNC16(so + j * 16,            pk0 + j * 4);
                CP_ASYNC16(so + ARRB + j * 16,     pk1 + j * 4);
                CP_ASYNC16(so + 2 * ARRB + j * 16, pq0 + j * 4);
                CP_ASYNC16(so + 3 * ARRB + j * 16, pq1 + j * 4);
            }
            CP_COMMIT();
            CP_WAIT0();
        }
        __syncthreads();

        float acc[4][4][4];
#pragma unroll
        for (int i = 0; i < 4; i++)
#pragma unroll
            for (int j = 0; j < 4; j++)
#pragma unroll
                for (int k = 0; k < 4; k++) acc[i][j][k] = 0.f;

        for (int kc = 0; kc < NCHUNK; kc++) {
            int cur = kc & 1;
            if (kc + 1 < NCHUNK) {
                size_t ko = (size_t)(kc + 1) * KC + half * 16;
                const float* pk0 = KH + (size_t)(l0 + lrow) * DIM + ko;
                const float* pk1 = KL + (size_t)(l0 + lrow) * DIM + ko;
                const float* pq0 = QH + (size_t)(q0 + lrow) * DIM + ko;
                const float* pq1 = QL + (size_t)(q0 + lrow) * DIM + ko;
                uint32_t so = sbase + (cur ^ 1) * BUFB + lrow * (KSTR * 4) + half * 64;
#pragma unroll
                for (int j = 0; j < 4; j++) {
                    CP_ASYNC16(so + j * 16,            pk0 + j * 4);
                    CP_ASYNC16(so + ARRB + j * 16,     pk1 + j * 4);
                    CP_ASYNC16(so + 2 * ARRB + j * 16, pq0 + j * 4);
                    CP_ASYNC16(so + 3 * ARRB + j * 16, pq1 + j * 4);
                }
                CP_COMMIT();
            }

            const float* Ah = smf + cur * (BUFB / 4);
            const float* Al = Ah + ARRF;
            const float* Bh = Al + ARRF;
            const float* Bl = Bh + ARRF;

#pragma unroll
            for (int k8 = 0; k8 < 4; k8++) {
                int k0 = k8 * 8;
                uint32_t ah[4][4], al[4][4], bh[4][2], bl[4][2];
#pragma unroll
                for (int mt = 0; mt < 4; mt++) {
                    int rb = warp_m * 64 + mt * 16;
                    ah[mt][0] = __float_as_uint(Ah[(rb + g) * KSTR + k0 + tig]);
                    ah[mt][1] = __float_as_uint(Ah[(rb + g + 8) * KSTR + k0 + tig]);
                    ah[mt][2] = __float_as_uint(Ah[(rb + g) * KSTR + k0 + tig + 4]);
                    ah[mt][3] = __float_as_uint(Ah[(rb + g + 8) * KSTR + k0 + tig + 4]);
                    al[mt][0] = __float_as_uint(Al[(rb + g) * KSTR + k0 + tig]);
                    al[mt][1] = __float_as_uint(Al[(rb + g + 8) * KSTR + k0 + tig]);
                    al[mt][2] = __float_as_uint(Al[(rb + g) * KSTR + k0 + tig + 4]);
                    al[mt][3] = __float_as_uint(Al[(rb + g + 8) * KSTR + k0 + tig + 4]);
                }
#pragma unroll
                for (int nt = 0; nt < 4; nt++) {
                    int qb = warp_n * 32 + nt * 8;
                    bh[nt][0] = __float_as_uint(Bh[(qb + g) * KSTR + k0 + tig]);
                    bh[nt][1] = __float_as_uint(Bh[(qb + g) * KSTR + k0 + tig + 4]);
                    bl[nt][0] = __float_as_uint(Bl[(qb + g) * KSTR + k0 + tig]);
                    bl[nt][1] = __float_as_uint(Bl[(qb + g) * KSTR + k0 + tig + 4]);
                }
#pragma unroll
                for (int mt = 0; mt < 4; mt++)
#pragma unroll
                    for (int nt = 0; nt < 4; nt++) {
                        MMA_TF32(acc[mt][nt], ah[mt], bh[nt]);
                        MMA_TF32(acc[mt][nt], ah[mt], bl[nt]);
                        MMA_TF32(acc[mt][nt], al[mt], bh[nt]);
                    }
            }
            CP_WAIT0();
            __syncthreads();
        }

        // ---- epilogue: per-column top-2 of this 128-row tile
#pragma unroll
        for (int nt = 0; nt < 4; nt++) {
#pragma unroll
            for (int par = 0; par < 2; par++) {
                float bv = -3.0e38f, sv = -3.0e38f;
                int bi = 0, si = 0;
#pragma unroll
                for (int mt = 0; mt < 4; mt++) {
                    int l1 = l0 + warp_m * 64 + mt * 16 + g;
                    float v = acc[mt][nt][par];
                    if (l1 < NL) {
                        if (v > bv)      { sv = bv; si = bi; bv = v; bi = l1; }
                        else if (v > sv) { sv = v; si = l1; }
                    }
                    int l2 = l1 + 8;
                    float v2 = acc[mt][nt][par + 2];
                    if (l2 < NL) {
                        if (v2 > bv)      { sv = bv; si = bi; bv = v2; bi = l2; }
                        else if (v2 > sv) { sv = v2; si = l2; }
                    }
                }
#pragma unroll
                for (int mk = 4; mk <= 16; mk <<= 1) {
                    float ov  = __shfl_xor_sync(0xffffffff, bv, mk);
                    int   oi  = __shfl_xor_sync(0xffffffff, bi, mk);
                    float ov2 = __shfl_xor_sync(0xffffffff, sv, mk);
                    int   oi2 = __shfl_xor_sync(0xffffffff, si, mk);
                    top2_merge(bv, bi, sv, si, ov, oi, ov2, oi2);
                }
                if (g == 0) {
                    int col = warp_n * 32 + nt * 8 + 2 * tig + par;
                    s2v[warp_m][col] = bv;  s2i[warp_m][col] = bi;
                    s2v2[warp_m][col] = sv; s2i2[warp_m][col] = si;
                }
            }
        }
        __syncthreads();
        if (tid < 128) {
            float bv = s_runv[tid], sv = s_runv2[tid];
            int bi = s_runi[tid], si = s_runi2[tid];
            top2_merge(bv, bi, sv, si, s2v[0][tid], s2i[0][tid], s2v2[0][tid], s2i2[0][tid]);
            top2_merge(bv, bi, sv, si, s2v[1][tid], s2i[1][tid], s2v2[1][tid], s2i2[1][tid]);
            s_runv[tid] = bv; s_runv2[tid] = sv;
            s_runi[tid] = bi; s_runi2[tid] = si;
        }
        __syncthreads();
    }

    if (tid < 128) {
        int q = q0 + tid;
        if (q < NL) {
            float bv = s_runv[tid], sv = s_runv2[tid];
            int bi = s_runi[tid], si = s_runi2[tid];
            S[b * NL + q]     = bv;
            g_arg[b * NL + q] = bi;
            if (bv - sv < MARGIN_TH) {
                int ix = atomicAdd(&g_nflag, 1);
                if (ix < MAXFLAG) g_flag[ix] = make_int4(b, q, bi, si);
            }
        }
    }
}

// ---------------------------------------------------------------------------
// Refine: near-tie queries, fp64-exact on the EXACT fp32 normalized operands
// (identical inputs/decisions to the validated R5 kernel).
// ---------------------------------------------------------------------------
__global__ __launch_bounds__(32) void fix_kernel() {
    int n = g_nflag; if (n > MAXFLAG) n = MAXFLAG;
    if ((int)blockIdx.x >= n) return;
    int4 f = g_flag[blockIdx.x];
    int b = f.x, q = f.y, i1 = f.z, i2 = f.w;
    const float* K1 = g_Kn + ((size_t)b * LPAD + i1) * DIM;
    const float* K2 = g_Kn + ((size_t)b * LPAD + i2) * DIM;
    const float* Qr = g_Qn + ((size_t)b * LPAD + q) * DIM;
    int lane = threadIdx.x;
    double s1 = 0.0, s2 = 0.0;
    for (int d = lane; d < DIM; d += 32) {
        double qq = (double)Qr[d];
        s1 = fma((double)K1[d], qq, s1);
        s2 = fma((double)K2[d], qq, s2);
    }
#pragma unroll
    for (int o = 16; o; o >>= 1) {
        s1 += __shfl_down_sync(0xffffffff, s1, o);
        s2 += __shfl_down_sync(0xffffffff, s2, o);
    }
    if (lane == 0) {
        int win;
        double gap = s1 - s2;
        if (fabs(gap) < TIE_ZONE) win = (i1 < i2) ? i1 : i2;
        else                      win = (gap > 0.0) ? i1 : i2;
        g_arg[b * NL + q] = win;
    }
}

// ---------------------------------------------------------------------------
// Gather: T[b, c*9+kh*3+kw, q] = value_padded[b, c, arg/96 + kh, arg%96 + kw]
// ---------------------------------------------------------------------------
__global__ __launch_bounds__(256) void gather_kernel(const float* __restrict__ value,
                                                     float* __restrict__ T) {
    int idx = blockIdx.x * 256 + threadIdx.x;
    const int total = BB * NE * NL;
    if (idx >= total) return;
    int q = idx % NL;
    int t = idx / NL;
    int e = t % NE;
    int b = t / NE;
    int l = g_arg[b * NL + q];
    int c = e / 9, k = e % 9;
    int kh = k / 3, kw = k % 3;
    int r  = l / 96 + kh - 1;
    int cc = l % 96 + kw - 1;
    float v = 0.f;
    if ((unsigned)r < HW && (unsigned)cc < HW)
        v = __ldg(&value[(((size_t)b * CCH + c) * HW + r) * HW + cc]);
    T[idx] = v;
}

// ---------------------------------------------------------------------------
extern "C" void kernel_launch(void* const* d_in, const int* in_sizes, int n_in,
                              void* d_out, int out_size) {
    const float* queue = (const float*)d_in[0];
    const float* key   = (const float*)d_in[1];
    const float* value = (const float*)d_in[2];
    float* out = (float*)d_out;            // layout: S (8*2209) then T (8*576*2209)

    cudaFuncSetAttribute(corr_kernel, cudaFuncAttributeMaxDynamicSharedMemorySize, SMEM_DYN);

    dim3 gp(NL, BB, 2);
    prep_kernel<<<gp, 256>>>(queue, key);

    dim3 gc(18, BB);
    corr_kernel<<<gc, 256, SMEM_DYN>>>(out);

    fix_kernel<<<MAXFLAG, 32>>>();

    const int total = BB * NE * NL;
    gather_kernel<<<(total + 255) / 256, 256>>>(value, out + BB * NL);
}

// round 11
// speedup vs baseline: 1.6768x; 1.6768x over previous
#include <cuda_runtime.h>
#include <cuda_fp16.h>
#include <cstdint>

// Problem constants
#define BB   8
#define CCH  64
#define HW   96
#define NL   2209      // 47*47 query/key patches
#define LPAD 2304      // padded to 18*128
#define DIM  1600      // 64*5*5 descriptor
#define NE   576       // 64*3*3 value patch dim
#define MAXFLAG 4096
#define MARGIN_TH 3e-4f
#define TIE_ZONE 8e-8  // fp64 gap below which we defer to first-occurrence rule

#define QTILE 128
#define LTILE 128
#define NLT   18
#define KC    32              // k-depth per chunk (halves)
#define NCHUNK (DIM/KC)       // 50
#define RSTRH 40              // smem row stride in halves (80B: 16B-aligned, conflict-free)
#define PANH  (128*RSTRH)     // halves per panel (5120)
#define PANB  (PANH*2)        // bytes per panel (10240)
#define BUFB  (4*PANB)        // 4 panels per buffer (40960)
#define BUFH  (4*PANH)
#define SMEM_DYN (2*BUFB)     // double buffered (81920)

// Scratch (zero-initialized .bss; rows [NL, LPAD) stay zero)
__device__ float  g_Qn [(size_t)BB * LPAD * DIM];   // exact normalized (refine)
__device__ float  g_Kn [(size_t)BB * LPAD * DIM];
__device__ __half g_Khi[(size_t)BB * LPAD * DIM];
__device__ __half g_Klo[(size_t)BB * LPAD * DIM];
__device__ __half g_Qhi[(size_t)BB * LPAD * DIM];
__device__ __half g_Qlo[(size_t)BB * LPAD * DIM];
__device__ int   g_arg[BB * NL];
__device__ int   g_nflag;
__device__ int4  g_flag[MAXFLAG];   // {b, q, best_idx, second_idx}

// ---------------------------------------------------------------------------
__device__ __forceinline__ uint32_t smem_u32(const void* p) {
    uint32_t a;
    asm("{ .reg .u64 t; cvta.to.shared.u64 t, %1; cvt.u32.u64 %0, t; }" : "=r"(a) : "l"(p));
    return a;
}

#define CP_ASYNC16(saddr, gptr) \
    asm volatile("cp.async.cg.shared.global [%0], [%1], 16;" :: "r"(saddr), "l"(gptr) : "memory")
#define CP_COMMIT() asm volatile("cp.async.commit_group;" ::: "memory")
#define CP_WAIT0()  asm volatile("cp.async.wait_group 0;" ::: "memory")

#define MMA_F16(c, a, b) \
    asm volatile( \
        "mma.sync.aligned.m16n8k16.row.col.f32.f16.f16.f32 " \
        "{%0,%1,%2,%3}, {%4,%5,%6,%7}, {%8,%9}, {%0,%1,%2,%3};" \
        : "+f"((c)[0]), "+f"((c)[1]), "+f"((c)[2]), "+f"((c)[3]) \
        : "r"((a)[0]), "r"((a)[1]), "r"((a)[2]), "r"((a)[3]), \
          "r"((b)[0]), "r"((b)[1]))

__device__ __forceinline__ void top2_merge(float& bv, int& bi, float& sv, int& si,
                                           float v, int iv, float v2, int i2) {
    if (v > bv || (v == bv && iv < bi)) {
        float ob = bv; int oi = bi;
        bv = v; bi = iv;
        if (ob > v2 || (ob == v2 && oi < i2)) { sv = ob; si = oi; }
        else { sv = v2; si = i2; }
    } else {
        if (v > sv || (v == sv && iv < si)) { sv = v; si = iv; }
    }
}

// ---------------------------------------------------------------------------
// Prep: unfold(5,1,2) + L2 normalize (fp64 norm); write exact fp32 + fp16 hi/lo.
// ---------------------------------------------------------------------------
__global__ __launch_bounds__(256) void prep_kernel(const float* __restrict__ queue,
                                                   const float* __restrict__ key) {
    int l = blockIdx.x;
    int b = blockIdx.y;
    bool isK = (blockIdx.z != 0);
    int t = threadIdx.x;
    if (blockIdx.x == 0 && blockIdx.y == 0 && blockIdx.z == 0 && t == 0) g_nflag = 0;

    const float* src = (isK ? key : queue) + (size_t)b * CCH * HW * HW;
    size_t ro = ((size_t)b * LPAD + l) * DIM;
    float*  dx = (isK ? g_Kn : g_Qn) + ro;
    __half* dh = (isK ? g_Khi : g_Qhi) + ro;
    __half* dl = (isK ? g_Klo : g_Qlo) + ro;

    int pi = l / 47, pj = l % 47;
    int r0 = pi * 2 - 1, c0 = pj * 2 - 1;

    float vals[7];
    double ss = 0.0;
#pragma unroll
    for (int it = 0; it < 7; it++) {
        int e = t + it * 256;
        float v = 0.f;
        if (e < DIM) {
            int c = e / 25, kk = e % 25;
            int r = r0 + kk / 5, cc = c0 + kk % 5;
            if ((unsigned)r < HW && (unsigned)cc < HW)
                v = src[((size_t)c * HW + r) * HW + cc];
        }
        vals[it] = v;
        ss += (double)v * (double)v;
    }

    __shared__ double red[256];
    red[t] = ss;
    __syncthreads();
    for (int s = 128; s >= 1; s >>= 1) {
        if (t < s) red[t] += red[t + s];
        __syncthreads();
    }
    float n = (float)sqrt(red[0]);
    if (n < 1e-12f) n = 1e-12f;

#pragma unroll
    for (int it = 0; it < 7; it++) {
        int e = t + it * 256;
        if (e < DIM) {
            float x = vals[it] / n;
            __half h = __float2half_rn(x);
            float hf = __half2float(h);
            __half lo = __float2half_rn(x - hf);
            dx[e] = x;
            dh[e] = h;
            dl[e] = lo;
        }
    }
}

// ---------------------------------------------------------------------------
// Fused correlation GEMM (3x FP16 m16n8k16 mma.sync) + column top-2 argmax.
// 256 threads (8 warps). Block tile 128L x 128Q; warp tile 64x32.
// K streamed in 32-half chunks via cp.async double buffering.
// ---------------------------------------------------------------------------
__global__ __launch_bounds__(256, 1) void corr_kernel(float* __restrict__ S) {
    int b  = blockIdx.y;
    int q0 = blockIdx.x * QTILE;
    const __half* KH = g_Khi + (size_t)b * LPAD * DIM;
    const __half* KL = g_Klo + (size_t)b * LPAD * DIM;
    const __half* QH = g_Qhi + (size_t)b * LPAD * DIM;
    const __half* QL = g_Qlo + (size_t)b * LPAD * DIM;

    extern __shared__ __half smh[];          // 2 buffers x 4 panels x 128 x 40 halves
    __shared__ float s2v[2][128], s2v2[2][128];
    __shared__ int   s2i[2][128], s2i2[2][128];
    __shared__ float s_runv[128], s_runv2[128];
    __shared__ int   s_runi[128], s_runi2[128];

    uint32_t sbase = smem_u32(smh);

    int tid = threadIdx.x;
    int wid = tid >> 5, lane = tid & 31;
    int g = lane >> 2, tig = lane & 3;
    int warp_m = wid >> 2;                   // 0..1 -> L halves
    int warp_n = wid & 3;                    // 0..3 -> Q quarters
    int lrow = tid & 127, half = tid >> 7;   // loader: 2 threads/row, 2x16B each/panel

    if (tid < 128) {
        s_runv[tid] = -3.0e38f; s_runv2[tid] = -3.0e38f;
        s_runi[tid] = 0; s_runi2[tid] = 0;
    }
    __syncthreads();

    for (int lt = 0; lt < NLT; lt++) {
        int l0 = lt * LTILE;

        // ---- prologue: chunk 0 -> buffer 0
        {
            const __half* pk0 = KH + (size_t)(l0 + lrow) * DIM + half * 16;
            const __half* pk1 = KL + (size_t)(l0 + lrow) * DIM + half * 16;
            const __half* pq0 = QH + (size_t)(q0 + lrow) * DIM + half * 16;
            const __half* pq1 = QL + (size_t)(q0 + lrow) * DIM + half * 16;
            uint32_t so = sbase + lrow * (RSTRH * 2) + half * 32;
#pragma unroll
            for (int j = 0; j < 2; j++) {
                CP_ASYNC16(so + j * 16,            pk0 + j * 8);
                CP_ASYNC16(so + PANB + j * 16,     pk1 + j * 8);
                CP_ASYNC16(so + 2 * PANB + j * 16, pq0 + j * 8);
                CP_ASYNC16(so + 3 * PANB + j * 16, pq1 + j * 8);
            }
            CP_COMMIT();
            CP_WAIT0();
        }
        __syncthreads();

        float acc[4][4][4];
#pragma unroll
        for (int i = 0; i < 4; i++)
#pragma unroll
            for (int j = 0; j < 4; j++)
#pragma unroll
                for (int k = 0; k < 4; k++) acc[i][j][k] = 0.f;

        for (int kc = 0; kc < NCHUNK; kc++) {
            int cur = kc & 1;
            if (kc + 1 < NCHUNK) {
                size_t ko = (size_t)(kc + 1) * KC + half * 16;
                const __half* pk0 = KH + (size_t)(l0 + lrow) * DIM + ko;
                const __half* pk1 = KL + (size_t)(l0 + lrow) * DIM + ko;
                const __half* pq0 = QH + (size_t)(q0 + lrow) * DIM + ko;
                const __half* pq1 = QL + (size_t)(q0 + lrow) * DIM + ko;
                uint32_t so = sbase + (cur ^ 1) * BUFB + lrow * (RSTRH * 2) + half * 32;
#pragma unroll
                for (int j = 0; j < 2; j++) {
                    CP_ASYNC16(so + j * 16,            pk0 + j * 8);
                    CP_ASYNC16(so + PANB + j * 16,     pk1 + j * 8);
                    CP_ASYNC16(so + 2 * PANB + j * 16, pq0 + j * 8);
                    CP_ASYNC16(so + 3 * PANB + j * 16, pq1 + j * 8);
                }
                CP_COMMIT();
            }

            const __half* Ah = smh + cur * BUFH;
            const __half* Al = Ah + PANH;
            const __half* Bh = Al + PANH;
            const __half* Bl = Bh + PANH;

#pragma unroll
            for (int kg = 0; kg < 2; kg++) {
                int k0 = kg * 16 + tig * 2;      // halves within row
                uint32_t ah[4][4], al[4][4], bh[4][2], bl[4][2];
#pragma unroll
                for (int mt = 0; mt < 4; mt++) {
                    int rb = warp_m * 64 + mt * 16;
                    ah[mt][0] = *(const uint32_t*)(Ah + (rb + g) * RSTRH + k0);
                    ah[mt][1] = *(const uint32_t*)(Ah + (rb + g + 8) * RSTRH + k0);
                    ah[mt][2] = *(const uint32_t*)(Ah + (rb + g) * RSTRH + k0 + 8);
                    ah[mt][3] = *(const uint32_t*)(Ah + (rb + g + 8) * RSTRH + k0 + 8);
                    al[mt][0] = *(const uint32_t*)(Al + (rb + g) * RSTRH + k0);
                    al[mt][1] = *(const uint32_t*)(Al + (rb + g + 8) * RSTRH + k0);
                    al[mt][2] = *(const uint32_t*)(Al + (rb + g) * RSTRH + k0 + 8);
                    al[mt][3] = *(const uint32_t*)(Al + (rb + g + 8) * RSTRH + k0 + 8);
                }
#pragma unroll
                for (int nt = 0; nt < 4; nt++) {
                    int qb = warp_n * 32 + nt * 8;
                    bh[nt][0] = *(const uint32_t*)(Bh + (qb + g) * RSTRH + k0);
                    bh[nt][1] = *(const uint32_t*)(Bh + (qb + g) * RSTRH + k0 + 8);
                    bl[nt][0] = *(const uint32_t*)(Bl + (qb + g) * RSTRH + k0);
                    bl[nt][1] = *(const uint32_t*)(Bl + (qb + g) * RSTRH + k0 + 8);
                }
#pragma unroll
                for (int mt = 0; mt < 4; mt++)
#pragma unroll
                    for (int nt = 0; nt < 4; nt++) {
                        MMA_F16(acc[mt][nt], ah[mt], bh[nt]);
                        MMA_F16(acc[mt][nt], ah[mt], bl[nt]);
                        MMA_F16(acc[mt][nt], al[mt], bh[nt]);
                    }
            }
            CP_WAIT0();
            __syncthreads();
        }

        // ---- epilogue: per-column top-2 of this 128-row tile
#pragma unroll
        for (int nt = 0; nt < 4; nt++) {
#pragma unroll
            for (int par = 0; par < 2; par++) {
                float bv = -3.0e38f, sv = -3.0e38f;
                int bi = 0, si = 0;
#pragma unroll
                for (int mt = 0; mt < 4; mt++) {
                    int l1 = l0 + warp_m * 64 + mt * 16 + g;
                    float v = acc[mt][nt][par];
                    if (l1 < NL) {
                        if (v > bv)      { sv = bv; si = bi; bv = v; bi = l1; }
                        else if (v > sv) { sv = v; si = l1; }
                    }
                    int l2 = l1 + 8;
                    float v2 = acc[mt][nt][par + 2];
                    if (l2 < NL) {
                        if (v2 > bv)      { sv = bv; si = bi; bv = v2; bi = l2; }
                        else if (v2 > sv) { sv = v2; si = l2; }
                    }
                }
#pragma unroll
                for (int mk = 4; mk <= 16; mk <<= 1) {
                    float ov  = __shfl_xor_sync(0xffffffff, bv, mk);
                    int   oi  = __shfl_xor_sync(0xffffffff, bi, mk);
                    float ov2 = __shfl_xor_sync(0xffffffff, sv, mk);
                    int   oi2 = __shfl_xor_sync(0xffffffff, si, mk);
                    top2_merge(bv, bi, sv, si, ov, oi, ov2, oi2);
                }
                if (g == 0) {
                    int col = warp_n * 32 + nt * 8 + 2 * tig + par;
                    s2v[warp_m][col] = bv;  s2i[warp_m][col] = bi;
                    s2v2[warp_m][col] = sv; s2i2[warp_m][col] = si;
                }
            }
        }
        __syncthreads();
        if (tid < 128) {
            float bv = s_runv[tid], sv = s_runv2[tid];
            int bi = s_runi[tid], si = s_runi2[tid];
            top2_merge(bv, bi, sv, si, s2v[0][tid], s2i[0][tid], s2v2[0][tid], s2i2[0][tid]);
            top2_merge(bv, bi, sv, si, s2v[1][tid], s2i[1][tid], s2v2[1][tid], s2i2[1][tid]);
            s_runv[tid] = bv; s_runv2[tid] = sv;
            s_runi[tid] = bi; s_runi2[tid] = si;
        }
        __syncthreads();
    }

    if (tid < 128) {
        int q = q0 + tid;
        if (q < NL) {
            float bv = s_runv[tid], sv = s_runv2[tid];
            int bi = s_runi[tid], si = s_runi2[tid];
            S[b * NL + q]     = bv;
            g_arg[b * NL + q] = bi;
            if (bv - sv < MARGIN_TH) {
                int ix = atomicAdd(&g_nflag, 1);
                if (ix < MAXFLAG) g_flag[ix] = make_int4(b, q, bi, si);
            }
        }
    }
}

// ---------------------------------------------------------------------------
// Refine: near-tie queries, fp64-exact on the EXACT fp32 normalized operands
// (identical decisions to the validated R5 kernel).
// ---------------------------------------------------------------------------
__global__ __launch_bounds__(32) void fix_kernel() {
    int n = g_nflag; if (n > MAXFLAG) n = MAXFLAG;
    if ((int)blockIdx.x >= n) return;
    int4 f = g_flag[blockIdx.x];
    int b = f.x, q = f.y, i1 = f.z, i2 = f.w;
    const float* K1 = g_Kn + ((size_t)b * LPAD + i1) * DIM;
    const float* K2 = g_Kn + ((size_t)b * LPAD + i2) * DIM;
    const float* Qr = g_Qn + ((size_t)b * LPAD + q) * DIM;
    int lane = threadIdx.x;
    double s1 = 0.0, s2 = 0.0;
    for (int d = lane; d < DIM; d += 32) {
        double qq = (double)Qr[d];
        s1 = fma((double)K1[d], qq, s1);
        s2 = fma((double)K2[d], qq, s2);
    }
#pragma unroll
    for (int o = 16; o; o >>= 1) {
        s1 += __shfl_down_sync(0xffffffff, s1, o);
        s2 += __shfl_down_sync(0xffffffff, s2, o);
    }
    if (lane == 0) {
        int win;
        double gap = s1 - s2;
        if (fabs(gap) < TIE_ZONE) win = (i1 < i2) ? i1 : i2;
        else                      win = (gap > 0.0) ? i1 : i2;
        g_arg[b * NL + q] = win;
    }
}

// ---------------------------------------------------------------------------
// Gather: T[b, c*9+kh*3+kw, q] = value_padded[b, c, arg/96 + kh, arg%96 + kw]
// ---------------------------------------------------------------------------
__global__ __launch_bounds__(256) void gather_kernel(const float* __restrict__ value,
                                                     float* __restrict__ T) {
    int idx = blockIdx.x * 256 + threadIdx.x;
    const int total = BB * NE * NL;
    if (idx >= total) return;
    int q = idx % NL;
    int t = idx / NL;
    int e = t % NE;
    int b = t / NE;
    int l = g_arg[b * NL + q];
    int c = e / 9, k = e % 9;
    int kh = k / 3, kw = k % 3;
    int r  = l / 96 + kh - 1;
    int cc = l % 96 + kw - 1;
    float v = 0.f;
    if ((unsigned)r < HW && (unsigned)cc < HW)
        v = __ldg(&value[(((size_t)b * CCH + c) * HW + r) * HW + cc]);
    T[idx] = v;
}

// ---------------------------------------------------------------------------
extern "C" void kernel_launch(void* const* d_in, const int* in_sizes, int n_in,
                              void* d_out, int out_size) {
    const float* queue = (const float*)d_in[0];
    const float* key   = (const float*)d_in[1];
    const float* value = (const float*)d_in[2];
    float* out = (float*)d_out;            // layout: S (8*2209) then T (8*576*2209)

    cudaFuncSetAttribute(corr_kernel, cudaFuncAttributeMaxDynamicSharedMemorySize, SMEM_DYN);

    dim3 gp(NL, BB, 2);
    prep_kernel<<<gp, 256>>>(queue, key);

    dim3 gc(18, BB);
    corr_kernel<<<gc, 256, SMEM_DYN>>>(out);

    fix_kernel<<<MAXFLAG, 32>>>();

    const int total = BB * NE * NL;
    gather_kernel<<<(total + 255) / 256, 256>>>(value, out + BB * NL);
}